// round 9
// baseline (speedup 1.0000x reference)
#include <cuda_runtime.h>

// ---------------------------------------------------------------------------
// TrackCrop: input [32, 512, 512, 3] f32 -> per-batch centroid -> 256x256 crop.
// SINGLE fused kernel, high occupancy: grid (64,32) x 384 threads.
//  Phase 1: packed-accumulator reduce, 8 rows/block, 1 float4/thread/row
//           (perfectly coalesced, 8 front-batched loads). Last block per
//           batch (ticket) computes the crop origin, publishes g_HW[b],
//           raises g_flag[b].
//  Phase 2: the 64 blocks of batch b spin on g_flag[b] (only after their own
//           contribution -> deadlock-free across waves), then copy 4 crop
//           rows each with coalesced scalar accesses (L2-hot reads).
//  All scratch returns to 0 each run -> graph-replay deterministic, no allocs.
// ---------------------------------------------------------------------------

#define NBATCH 32
#define SY 512
#define SX 512
#define NC 3
#define ROW_FLOATS (SX * NC)        // 1536
#define ROW_F4 (ROW_FLOATS / 4)     // 384
#define CROP 256
#define OUT_ROW_FLOATS (CROP * NC)  // 768

#define NT 384                      // threads per block (= ROW_F4)
#define RB 8                        // rows per block (reduce)
#define BLOCKS_PER_BATCH (SY / RB)  // 64
#define CROWS (CROP / BLOCKS_PER_BATCH) // 4 crop rows per block

#define CNT_ONE (1 << 20)           // cnt above bit 20; sx below
#define SX_MASK (CNT_ONE - 1)

__device__ int  g_cnt[NBATCH];   // zero at load; returned to 0 every run
__device__ int  g_sx[NBATCH];
__device__ int  g_sy[NBATCH];
__device__ int  g_tick[NBATCH];
__device__ int  g_flag[NBATCH];
__device__ int  g_tick2[NBATCH];
__device__ int2 g_HW[NBATCH];    // (H, W) crop origin per batch

__global__ __launch_bounds__(NT) void fused_kernel(const float* __restrict__ in,
                                                   float* __restrict__ out) {
    const int t  = threadIdx.x;             // 0..383
    const int b  = blockIdx.y;              // 0..31
    const int bx = blockIdx.x;              // 0..63
    const int y0 = bx * RB;

    // ---------------- Phase 1: reduce (packed accumulator) ----------------
    // This thread's 4 float lanes: j = 4t..4t+3; packed weight = x + CNT_ONE.
    const int j = 4 * t;
    int w0 = (j    ) / 3 + CNT_ONE;
    int w1 = (j + 1) / 3 + CNT_ONE;
    int w2 = (j + 2) / 3 + CNT_ONE;
    int w3 = (j + 3) / 3 + CNT_ONE;

    const float4* __restrict__ base =
        (const float4*)(in + ((size_t)b * SY + y0) * ROW_FLOATS) + t;

    int accT = 0;   // packed: sx [0,20), cnt [20,..)   (cnt <= 32, sx < 2^20)
    int sy   = 0;
    #pragma unroll
    for (int r = 0; r < RB; r++) {
        const float4 a = base[(size_t)r * ROW_F4];
        int acc = 0;
        if (a.x != 0.0f) acc += w0;
        if (a.y != 0.0f) acc += w1;
        if (a.z != 0.0f) acc += w2;
        if (a.w != 0.0f) acc += w3;
        accT += acc;
        sy   += (y0 + r) * (acc >> 20);
    }

    int cnt = accT >> 20;
    int sx  = accT & SX_MASK;

    #pragma unroll
    for (int o = 16; o > 0; o >>= 1) {
        cnt += __shfl_down_sync(0xFFFFFFFFu, cnt, o);
        sx  += __shfl_down_sync(0xFFFFFFFFu, sx,  o);
        sy  += __shfl_down_sync(0xFFFFFFFFu, sy,  o);
    }

    __shared__ int s_cnt, s_sx, s_sy;
    if (t == 0) { s_cnt = 0; s_sx = 0; s_sy = 0; }
    __syncthreads();
    if ((t & 31) == 0) {
        atomicAdd(&s_cnt, cnt);
        atomicAdd(&s_sx,  sx);
        atomicAdd(&s_sy,  sy);
    }
    __syncthreads();

    if (t == 0) {
        atomicAdd(&g_cnt[b], s_cnt);
        atomicAdd(&g_sx[b],  s_sx);
        atomicAdd(&g_sy[b],  s_sy);
        __threadfence();
        if (atomicAdd(&g_tick[b], 1) == BLOCKS_PER_BATCH - 1) {
            // Finalizer: read+reset scratch, publish origin, raise flag.
            const int c  = atomicExch(&g_cnt[b], 0);
            const int xs = atomicExch(&g_sx[b],  0);
            const int ys = atomicExch(&g_sy[b],  0);
            atomicExch(&g_tick[b], 0);
            // Reference numerics: int32->f32 RN, IEEE f32 divide, trunc cast.
            const float fc = __int2float_rn(c);
            const int xcm = (int)__fdiv_rn(__int2float_rn(xs), fc);
            const int ycm = (int)__fdiv_rn(__int2float_rn(ys), fc);
            int2 hw;
            hw.x = min(max(ycm - CROP / 2, 0), SY - 1 - CROP);  // H
            hw.y = min(max(xcm - CROP / 2, 0), SX - 1 - CROP);  // W
            g_HW[b] = hw;
            __threadfence();
            atomicExch(&g_flag[b], 1);
        }
    }

    // ------------- Spin until this batch's origin is published -------------
    // Safe across waves: we only spin after contributing; completed batches
    // retire and free SMs for the remaining blocks of a partial batch.
    if (t == 0) {
        while (atomicAdd(&g_flag[b], 0) == 0) {
            __nanosleep(64);
        }
    }
    __syncthreads();

    const int hH = ((volatile int*)&g_HW[b].x)[0];
    const int hW = ((volatile int*)&g_HW[b].y)[0];

    // ---------------- Phase 2: crop 4 rows per block -----------------------
    const float* __restrict__ inb  = in  + (size_t)b * (SY * SX * NC);
    float* __restrict__       outb = out + (size_t)b * (CROP * OUT_ROW_FLOATS);

    #pragma unroll
    for (int rr = 0; rr < CROWS; rr++) {
        const int row = bx * CROWS + rr;                 // output row
        const float* __restrict__ src =
            inb + ((size_t)(hH + row) * SX + hW) * NC + t;
        float* __restrict__ dst =
            outb + (size_t)row * OUT_ROW_FLOATS + t;
        const float v0 = src[0];
        const float v1 = src[NT];
        dst[0]  = v0;
        dst[NT] = v1;
    }

    // ---------------- Reset flag for next graph replay ---------------------
    __syncthreads();
    if (t == 0) {
        if (atomicAdd(&g_tick2[b], 1) == BLOCKS_PER_BATCH - 1) {
            atomicExch(&g_tick2[b], 0);
            atomicExch(&g_flag[b],  0);
        }
    }
}

extern "C" void kernel_launch(void* const* d_in, const int* in_sizes, int n_in,
                              void* d_out, int out_size) {
    const float* in = (const float*)d_in[0];
    float* out = (float*)d_out;

    fused_kernel<<<dim3(BLOCKS_PER_BATCH, NBATCH), NT>>>(in, out);
}

// round 11
// speedup vs baseline: 1.4656x; 1.4656x over previous
#include <cuda_runtime.h>

// ---------------------------------------------------------------------------
// TrackCrop: input [32, 512, 512, 3] f32.
// Two kernels (fusion measured slower):
//  reduce: grid (64,32) x 128 thr, 8 rows/block -> ~75% occupancy (the R3
//          version was grid-limited to ~22%). Packed accumulator: one
//          predicated IADD per element carries sx (low 20b) + cnt (high).
//          Ticket finalizer publishes crop origin, scratch self-resets.
//  crop:   best-measured variant (R3): 192 thr, 8 rows/block, scalar loads
//          (src only 4B-aligned) + float4 stores.
// ---------------------------------------------------------------------------

#define NBATCH 32
#define SY 512
#define SX 512
#define NC 3
#define ROW_FLOATS (SX * NC)        // 1536
#define ROW_F4 (ROW_FLOATS / 4)     // 384
#define CROP 256
#define OUT_ROW_FLOATS (CROP * NC)  // 768

#define RB 8                        // rows per reduce block
#define RBLOCKS_PER_BATCH (SY / RB) // 64

#define CR 8                        // rows per crop block
#define CBLOCKS_PER_BATCH (CROP / CR) // 32

#define CNT_ONE (1 << 20)           // cnt above bit 20; sx below
#define SX_MASK (CNT_ONE - 1)

__device__ int  g_cnt[NBATCH];   // zero at load; returned to 0 every run
__device__ int  g_sx[NBATCH];
__device__ int  g_sy[NBATCH];
__device__ int  g_tick[NBATCH];
__device__ int2 g_HW[NBATCH];    // (H, W) crop origin per batch

__global__ __launch_bounds__(128) void reduce_kernel(const float* __restrict__ in) {
    const int t  = threadIdx.x;             // 0..127
    const int b  = blockIdx.y;              // 0..31
    const int y0 = blockIdx.x * RB;         // 0,8,...,504

    // Per-lane packed weights: x-coordinate + CNT_ONE, hoisted out of loop.
    int w[12];
    #pragma unroll
    for (int i = 0; i < 3; i++) {
        const int j = 4 * (t + i * 128);    // float index within row
        #pragma unroll
        for (int k = 0; k < 4; k++)
            w[i * 4 + k] = (j + k) / 3 + CNT_ONE;
    }

    const float4* __restrict__ base =
        (const float4*)(in + ((size_t)b * SY + y0) * ROW_FLOATS);

    int accT = 0;   // packed: sx [0,20), cnt [20,..)  (cnt<=96, sx<=49K: safe)
    int sy   = 0;
    #pragma unroll
    for (int r = 0; r < RB; r++) {
        const float4* __restrict__ row = base + (size_t)r * ROW_F4;
        const float4 a = row[t];
        const float4 c = row[t + 128];
        const float4 d = row[t + 256];

        int acc = 0;
        if (a.x != 0.0f) acc += w[0];
        if (a.y != 0.0f) acc += w[1];
        if (a.z != 0.0f) acc += w[2];
        if (a.w != 0.0f) acc += w[3];
        if (c.x != 0.0f) acc += w[4];
        if (c.y != 0.0f) acc += w[5];
        if (c.z != 0.0f) acc += w[6];
        if (c.w != 0.0f) acc += w[7];
        if (d.x != 0.0f) acc += w[8];
        if (d.y != 0.0f) acc += w[9];
        if (d.z != 0.0f) acc += w[10];
        if (d.w != 0.0f) acc += w[11];

        accT += acc;
        sy   += (y0 + r) * (acc >> 20);     // row count
    }

    int cnt = accT >> 20;
    int sx  = accT & SX_MASK;

    // warp reduce
    #pragma unroll
    for (int o = 16; o > 0; o >>= 1) {
        cnt += __shfl_down_sync(0xFFFFFFFFu, cnt, o);
        sx  += __shfl_down_sync(0xFFFFFFFFu, sx,  o);
        sy  += __shfl_down_sync(0xFFFFFFFFu, sy,  o);
    }

    __shared__ int s_cnt, s_sx, s_sy;
    if (t == 0) { s_cnt = 0; s_sx = 0; s_sy = 0; }
    __syncthreads();
    if ((t & 31) == 0) {
        atomicAdd(&s_cnt, cnt);
        atomicAdd(&s_sx,  sx);
        atomicAdd(&s_sy,  sy);
    }
    __syncthreads();

    if (t == 0) {
        atomicAdd(&g_cnt[b], s_cnt);
        atomicAdd(&g_sx[b],  s_sx);
        atomicAdd(&g_sy[b],  s_sy);
        __threadfence();
        if (atomicAdd(&g_tick[b], 1) == RBLOCKS_PER_BATCH - 1) {
            // Last block for this batch: read+reset (scratch back to 0 for
            // the next graph replay), publish crop origin.
            const int c  = atomicExch(&g_cnt[b], 0);
            const int xs = atomicExch(&g_sx[b],  0);
            const int ys = atomicExch(&g_sy[b],  0);
            atomicExch(&g_tick[b], 0);
            // Reference numerics: int32->f32 RN, IEEE f32 divide, trunc cast.
            const float fc = __int2float_rn(c);
            const int xcm = (int)__fdiv_rn(__int2float_rn(xs), fc);
            const int ycm = (int)__fdiv_rn(__int2float_rn(ys), fc);
            int2 hw;
            hw.x = min(max(ycm - CROP / 2, 0), SY - 1 - CROP);  // H
            hw.y = min(max(xcm - CROP / 2, 0), SX - 1 - CROP);  // W
            g_HW[b] = hw;
        }
    }
}

// Best-measured crop: 192 threads, 8 output rows per block. Scalar loads
// (source only 4B-aligned since W*3 is arbitrary), aligned float4 stores.
__global__ __launch_bounds__(192) void crop_kernel(const float* __restrict__ in,
                                                   float* __restrict__ out) {
    const int t  = threadIdx.x;          // 0..191
    const int b  = blockIdx.y;           // batch
    const int r0 = blockIdx.x * CR;      // first output row of this block

    const int2 hw = g_HW[b];             // (H, W)

    const float* __restrict__ srcb =
        in + (size_t)b * (SY * SX * NC)
           + ((size_t)(hw.x + r0) * SX + hw.y) * NC
           + 4 * t;
    float4* __restrict__ dstb =
        (float4*)(out + ((size_t)b * CROP + r0) * OUT_ROW_FLOATS) + t;

    #pragma unroll
    for (int r = 0; r < CR; r++) {
        const float* __restrict__ src = srcb + (size_t)r * ROW_FLOATS;
        float4 v;
        v.x = src[0];
        v.y = src[1];
        v.z = src[2];
        v.w = src[3];
        dstb[(size_t)r * (OUT_ROW_FLOATS / 4)] = v;
    }
}

extern "C" void kernel_launch(void* const* d_in, const int* in_sizes, int n_in,
                              void* d_out, int out_size) {
    const float* in = (const float*)d_in[0];
    float* out = (float*)d_out;

    reduce_kernel<<<dim3(RBLOCKS_PER_BATCH, NBATCH), 128>>>(in);
    crop_kernel<<<dim3(CBLOCKS_PER_BATCH, NBATCH), 192>>>(in, out);
}